// round 16
// baseline (speedup 1.0000x reference)
#include <cuda_runtime.h>
#include <cstdint>
#include <math.h>

#define NN 30000
#define EE 100000
#define DD 200
#define RR 100
#define BB 50
#define OUT4 (4*DD)   // 800 packed output columns: k,q,v,s

typedef unsigned long long ULL;

// ---------------- packed f32x2 helpers (FFMA2: 2x fp32 FMA throughput) ----------------
__device__ __forceinline__ ULL pk2(float a, float b) {
  ULL r; asm("mov.b64 %0,{%1,%2};" : "=l"(r) : "f"(a), "f"(b)); return r;
}
__device__ __forceinline__ void upk2(ULL d, float& x, float& y) {
  asm("mov.b64 {%0,%1},%2;" : "=f"(x), "=f"(y) : "l"(d));
}
__device__ __forceinline__ void fma2(ULL& d, ULL a, ULL b) {
  asm("fma.rn.f32x2 %0,%1,%2,%0;" : "+l"(d) : "l"(a), "l"(b));
}

// ---------------- scratch (static device globals; no runtime alloc) ----------------
__device__ __align__(16) float g_M[RR*DD*DD];        // per-relation matrices, 16MB
__device__ __align__(16) float g_W4T[DD*OUT4];       // packed weights, k-major [200][800]
__device__ __align__(16) float g_XT[DD*NN];          // transposed X, k-major [200][30000]
__device__ __align__(16) float g_WRT[DD*DD];         // transposed wR, k-major [200][200]
__device__ float g_b4[OUT4];
__device__ __align__(16) float g_KQVS[4u*NN*DD];     // K|Q|V|S node features, 96MB
__device__ unsigned g_maxu[NN];
__device__ __align__(16) float g_agg[NN*DD];         // n_pre (merged) output
__device__ int g_cnt[RR];
__device__ int g_off[RR+1];
__device__ int g_cur[RR];
__device__ int g_eid[EE];
__device__ int g_cnt2[NN];      // dst histogram
__device__ int g_off2[NN+1];
__device__ int g_cur2[NN];
__device__ int g_p2[EE];        // e -> dst-sorted position
__device__ int g_src2[EE];      // src, dst-sorted
__device__ float g_att2[EE];    // att, dst-sorted
__device__ float g_colsum[DD];
__device__ float g_colsum2[DD];
__device__ float g_scale[DD];
__device__ float g_shift[DD];
__device__ int g_done;

// ---------------- fused prep: pack W4T, biases, transpose X and wR, init counters -------
#define PB_PACK 625                      // OUT4*DD/256
#define PB_PACKB 25
#define NTX 938                          // ceil(NN/32)
#define PB_TX (NTX*7)                    // 6566
#define PB_TR 49                         // 7*7
#define PB_INIT 118                      // ceil(30000/256)
#define PREP_GRID (PB_PACK + PB_PACKB + PB_TX + PB_TR + PB_INIT)   // 7383
__global__ __launch_bounds__(256) void k_prep(
    const float* __restrict__ kw, const float* __restrict__ qw,
    const float* __restrict__ vw, const float* __restrict__ sw,
    const float* __restrict__ kb, const float* __restrict__ qb,
    const float* __restrict__ vb, const float* __restrict__ sb,
    const float* __restrict__ loop, const float* __restrict__ X,
    const float* __restrict__ wR) {
  __shared__ float tsh[32][33];
  int b = blockIdx.x, t = threadIdx.x;
  if (b < PB_PACK) {                         // ---- pack W4T[i][o]
    int idx = b*256 + t;
    if (idx < OUT4*DD) {
      int i = idx / OUT4, o = idx - i*OUT4;
      int z = o / DD, j = o - z*DD;
      const float* w = (z==0)?kw:(z==1)?qw:(z==2)?vw:sw;
      g_W4T[idx] = w[(size_t)j*DD + i];
    }
  } else if (b < PB_PACK + PB_PACKB) {       // ---- biases
    int blk = b - PB_PACK;
    int g = blk*256 + t;
    if (g < 600) {
      int z = g / DD, j = g - z*DD;
      g_b4[g] = (z==0)?kb[j]:(z==1)?qb[j]:vb[j];
    }
    int w = blk*8 + (t >> 5);
    int lane = t & 31;
    if (w < DD) {
      float acc = 0.f;
      for (int i = lane; i < DD; i += 32) acc = fmaf(loop[i], sw[(size_t)w*DD + i], acc);
      #pragma unroll
      for (int o = 16; o; o >>= 1) acc += __shfl_xor_sync(0xffffffffu, acc, o);
      if (lane == 0) g_b4[600 + w] = sb[w] - acc;
    }
  } else if (b < PB_PACK + PB_PACKB + PB_TX) {  // ---- transpose X
    int b2 = b - (PB_PACK + PB_PACKB);
    int bxi = (b2 % NTX)*32, byi = (b2 / NTX)*32;
    int tx = t & 31, ty = t >> 5;
    #pragma unroll
    for (int i = 0; i < 32; i += 8) {
      int n = bxi + ty + i, d = byi + tx;
      tsh[ty+i][tx] = (n < NN && d < DD) ? X[(size_t)n*DD + d] : 0.f;
    }
    __syncthreads();
    #pragma unroll
    for (int i = 0; i < 32; i += 8) {
      int d = byi + ty + i, n = bxi + tx;
      if (d < DD && n < NN) g_XT[(size_t)d*NN + n] = tsh[tx][ty+i];
    }
  } else if (b < PB_PACK + PB_PACKB + PB_TX + PB_TR) {  // ---- transpose wR
    int b2 = b - (PB_PACK + PB_PACKB + PB_TX);
    int bxi = (b2 % 7)*32, byi = (b2 / 7)*32;
    int tx = t & 31, ty = t >> 5;
    #pragma unroll
    for (int i = 0; i < 32; i += 8) {
      int j = bxi + ty + i, c = byi + tx;
      tsh[ty+i][tx] = (j < DD && c < DD) ? wR[(size_t)j*DD + c] : 0.f;
    }
    __syncthreads();
    #pragma unroll
    for (int i = 0; i < 32; i += 8) {
      int c = byi + ty + i, j = bxi + tx;
      if (c < DD && j < DD) g_WRT[(size_t)c*DD + j] = tsh[tx][ty+i];
    }
  } else {                                   // ---- init counters
    int idx = (b - (PB_PACK + PB_PACKB + PB_TX + PB_TR))*256 + t;
    if (idx < NN) { g_maxu[idx] = 0x007FFFFFu; g_cnt2[idx] = 0; g_cur2[idx] = 0; }
    if (idx < RR) { g_cnt[idx] = 0; g_cur[idx] = 0; }
    if (idx < DD) { g_colsum[idx] = 0.f; g_colsum2[idx] = 0.f; }
    if (idx == 0) g_done = 0;
  }
}

// ---------------- fused GEMM -> K,Q,V,S (f32x2, 512 thr, GBK=32 guard-free loads) ------
#define GBM 128
#define GBN 128
#define GBK 32
#define NPH 7
#define GSTG (GBK*GBM)            // 4096 floats per matrix per buffer
#define GEMM_SMEM (4*GSTG*4)      // 65536 B : A0|A1|B0|B1
__global__ __launch_bounds__(512) void k_gemm() {
  extern __shared__ __align__(16) float sm[];
  float* Ab[2] = { sm,            sm + GSTG   };
  float* Bb[2] = { sm + 2*GSTG,   sm + 3*GSTG };
  int row0 = blockIdx.x*GBM, col0 = blockIdx.y*GBN;
  int tid = threadIdx.x;
  int r2 = tid >> 5, c2 = tid & 31;      // per-l: row = r2 + l*16, col = c2
  int gmc = row0 + c2*4, goc = col0 + c2*4;
  bool okA = (gmc + 3 < NN);
  bool okB = (goc + 3 < OUT4);
  const float* Asrc = g_XT + gmc;
  const float* Bsrc = g_W4T + goc;

  float4 rA[2], rB[2];
  #define LD_PH(k0) do { \
    _Pragma("unroll") \
    for (int l = 0; l < 2; l++) { \
      int r = r2 + l*16; \
      bool ok = ((k0) + r) < DD;   /* const-folds for phases 0..5 */ \
      rA[l] = (okA && ok) ? *(const float4*)(Asrc + (size_t)((k0)+r)*NN)   \
                          : make_float4(0.f,0.f,0.f,0.f); \
      rB[l] = (okB && ok) ? *(const float4*)(Bsrc + (size_t)((k0)+r)*OUT4) \
                          : make_float4(0.f,0.f,0.f,0.f); \
    } \
  } while(0)
  #define ST_PH(bf) do { \
    _Pragma("unroll") \
    for (int l = 0; l < 2; l++) { \
      int r = r2 + l*16; \
      *(float4*)&Ab[bf][r*GBM + c2*4] = rA[l]; \
      *(float4*)&Bb[bf][r*GBN + c2*4] = rB[l]; \
    } \
  } while(0)

  // 4x4 warps (32x32 warp tile), lanes 4x8, 8x4 thread tile
  int w = tid >> 5, lane = tid & 31;
  int wm = w & 3, wn = w >> 2;
  int lm = lane >> 3, ln = lane & 7;
  int m0 = wm*32 + lm*8;
  int n0 = wn*32 + ln*4;

  ULL acc[8][2];
  #pragma unroll
  for (int u = 0; u < 8; u++) { acc[u][0] = pk2(0.f,0.f); acc[u][1] = pk2(0.f,0.f); }

  LD_PH(0); ST_PH(0);
  __syncthreads();
  #pragma unroll
  for (int s = 0; s < NPH; s++) {
    int bf = s & 1;
    if (s + 1 < NPH) LD_PH((s+1)*GBK);   // LDG in flight during compute below
    const float* A = Ab[bf];
    const float* B = Bb[bf];
    #pragma unroll 4
    for (int kk = 0; kk < GBK; kk++) {
      float4 a0 = *(const float4*)&A[kk*GBM + m0];
      float4 a1 = *(const float4*)&A[kk*GBM + m0 + 4];
      float4 b0 = *(const float4*)&B[kk*GBN + n0];
      ULL bb0 = ((const ULL*)&b0)[0], bb1 = ((const ULL*)&b0)[1];
      float av[8] = {a0.x,a0.y,a0.z,a0.w,a1.x,a1.y,a1.z,a1.w};
      #pragma unroll
      for (int u = 0; u < 8; u++) {
        ULL aa = pk2(av[u], av[u]);
        fma2(acc[u][0], aa, bb0);
        fma2(acc[u][1], aa, bb1);
      }
    }
    if (s + 1 < NPH) ST_PH((s+1)&1);
    __syncthreads();
  }

  // epilogue: 8 rows x 4 cols per thread; 4-col groups never straddle z-boundary
  int o0 = col0 + n0;
  if (o0 < OUT4) {
    int z = o0 / DD, j0 = o0 - z*DD;
    float4 bi = *(const float4*)&g_b4[o0];
    float* outb = g_KQVS + (size_t)z*NN*DD + j0;
    #pragma unroll
    for (int u = 0; u < 8; u++) {
      int n = row0 + m0 + u;
      if (n >= NN) continue;
      float c0,c1,c2v,c3;
      upk2(acc[u][0], c0, c1); upk2(acc[u][1], c2v, c3);
      *(float4*)(outb + (size_t)n*DD) =
        make_float4(c0+bi.x, c1+bi.y, c2v+bi.z, c3+bi.w);
    }
  }
  #undef LD_PH
  #undef ST_PH
}

// ---------------- M_r = sum_b w_comp[r,b] * A_b  (register-cached) ----------------
__global__ __launch_bounds__(256) void k_compM(const float* __restrict__ A,
                                               const float* __restrict__ wc) {
  __shared__ float wsh[RR*BB];   // 20KB
  int tid = threadIdx.x;
  for (int idx = tid; idx < RR*BB; idx += 256) wsh[idx] = wc[idx];
  __syncthreads();
  int n = blockIdx.x*256 + tid;
  if (n >= DD*DD) return;
  float a[BB];
  #pragma unroll
  for (int b = 0; b < BB; b++) a[b] = A[(size_t)b*DD*DD + n];
  for (int r = 0; r < RR; r++) {
    float acc0 = 0.f, acc1 = 0.f;
    const float* wr = wsh + r*BB;
    #pragma unroll
    for (int b = 0; b < BB; b += 2) {
      acc0 = fmaf(wr[b],   a[b],   acc0);
      acc1 = fmaf(wr[b+1], a[b+1], acc1);
    }
    g_M[(size_t)r*DD*DD + n] = acc0 + acc1;
  }
}

// ---------------- histograms: by relation AND by dst ----------------
__global__ void k_hist(const int* __restrict__ et, const int* __restrict__ dst) {
  int e = blockIdx.x*blockDim.x + threadIdx.x;
  if (e < EE) {
    atomicAdd(&g_cnt[et[e]], 1);
    atomicAdd(&g_cnt2[dst[e]], 1);
  }
}

// ---------------- fused scans: relation offsets (parallel) + dst offsets ----------------
#define SC_CHUNK 30
__global__ __launch_bounds__(1024) void k_scan12() {
  __shared__ int ps[1024];
  __shared__ int rs[128];
  int t = threadIdx.x;
  // relation scan (128-wide Hillis-Steele over RR=100)
  if (t < 128) rs[t] = (t < RR) ? g_cnt[t] : 0;
  __syncthreads();
  for (int off = 1; off < 128; off <<= 1) {
    int a = 0;
    if (t < 128) { a = rs[t]; if (t >= off) a += rs[t-off]; }
    __syncthreads();
    if (t < 128) rs[t] = a;
    __syncthreads();
  }
  if (t < RR) g_off[t] = (t == 0) ? 0 : rs[t-1];
  if (t == 0) g_off[RR] = rs[RR-1];
  __syncthreads();
  // dst scan over NN
  int base = t*SC_CHUNK;
  int s = 0;
  #pragma unroll
  for (int i = 0; i < SC_CHUNK; i++) { int idx = base+i; if (idx < NN) s += g_cnt2[idx]; }
  ps[t] = s;
  __syncthreads();
  for (int off = 1; off < 1024; off <<= 1) {
    int v = ps[t];
    int add = (t >= off) ? ps[t-off] : 0;
    __syncthreads();
    ps[t] = v + add;
    __syncthreads();
  }
  int run = (t > 0) ? ps[t-1] : 0;
  #pragma unroll
  for (int i = 0; i < SC_CHUNK; i++) {
    int idx = base+i;
    if (idx < NN) { g_off2[idx] = run; run += g_cnt2[idx]; }
  }
  if (t == 1023) g_off2[NN] = ps[1023];
}
__global__ void k_scatter(const int* __restrict__ et, const int* __restrict__ src,
                          const int* __restrict__ dst) {
  int e = blockIdx.x*blockDim.x + threadIdx.x;
  if (e < EE) {
    int t = et[e];
    int p = atomicAdd(&g_cur[t], 1);
    g_eid[g_off[t] + p] = e;
    int d = dst[e];
    int p2 = atomicAdd(&g_cur2[d], 1);
    int pos = g_off2[d] + p2;
    g_p2[e] = pos;
    g_src2[pos] = src[e];
  }
}

// ---------------- attention: att_e = k^T M_r q (f32x2), 256 thr, 4 rows/thread ----------
#define ABM 128
#define KST 204
#define ATT_SMEM ((ABM*KST + DD*64 + ABM*64 + ABM)*4 + 3*ABM*4)  // 190464 B
__global__ __launch_bounds__(256, 1) void k_att(const int* __restrict__ src,
                                                const int* __restrict__ dst) {
  extern __shared__ __align__(16) float sm[];
  float* k_sh   = sm;                 // [ABM][KST]
  float* Msh    = k_sh + ABM*KST;     // [DD][64] (reused as [DD][8] in remainder)
  float* q_t    = Msh + DD*64;        // [ABM][64] (reused as [ABM][8])
  float* att_sh = q_t + ABM*64;       // [ABM]
  int* es_src = (int*)(att_sh + ABM);
  int* es_dst = es_src + ABM;
  int* es_eid = es_dst + ABM;

  int r = blockIdx.x;
  int beg = g_off[r], end = g_off[r+1];
  int base = beg + blockIdx.y*ABM;
  if (base >= end) return;
  int m = end - base; if (m > ABM) m = ABM;
  int tid = threadIdx.x;
  if (tid < ABM) {
    int e = g_eid[base + ((tid < m) ? tid : 0)];
    es_eid[tid] = e;
    es_src[tid] = src[e];
    es_dst[tid] = dst[e];
    att_sh[tid] = 0.f;
  }
  __syncthreads();
  for (int idx = tid; idx < ABM*(DD/4); idx += 256) {
    int e = idx / (DD/4), p = idx - e*(DD/4);
    *(float4*)(k_sh + e*KST + p*4) = *(const float4*)(g_KQVS + (size_t)es_src[e]*DD + p*4);
  }
  int tx = tid & 7;
  int ty = tid >> 3;        // 0..31, 4 rows each
  const float* Mr = g_M + (size_t)r*DD*DD;
  const float* Qbase = g_KQVS + (size_t)NN*DD;
  for (int jt = 0; jt < 3; jt++) {
    int j0 = jt*64;
    __syncthreads();
    for (int idx = tid; idx < DD*16; idx += 256) {
      int i = idx >> 4, p = idx & 15;
      *(float4*)(Msh + i*64 + p*4) = *(const float4*)(Mr + (size_t)i*DD + j0 + p*4);
    }
    for (int idx = tid; idx < ABM*16; idx += 256) {
      int e = idx >> 4, p = idx & 15;
      *(float4*)(q_t + e*64 + p*4) = *(const float4*)(Qbase + (size_t)es_dst[e]*DD + j0 + p*4);
    }
    __syncthreads();
    ULL acc[4][4];
    #pragma unroll
    for (int u = 0; u < 4; u++)
      #pragma unroll
      for (int v = 0; v < 4; v++) acc[u][v] = pk2(0.f, 0.f);
    #pragma unroll 4
    for (int kk = 0; kk < DD; kk++) {
      float4 b0 = *(const float4*)(Msh + kk*64 + tx*8);
      float4 b1 = *(const float4*)(Msh + kk*64 + tx*8 + 4);
      ULL bb0 = ((const ULL*)&b0)[0], bb1 = ((const ULL*)&b0)[1];
      ULL bb2 = ((const ULL*)&b1)[0], bb3 = ((const ULL*)&b1)[1];
      #pragma unroll
      for (int u = 0; u < 4; u++) {
        float a = k_sh[(ty*4+u)*KST + kk];
        ULL aa = pk2(a, a);
        fma2(acc[u][0], aa, bb0); fma2(acc[u][1], aa, bb1);
        fma2(acc[u][2], aa, bb2); fma2(acc[u][3], aa, bb3);
      }
    }
    #pragma unroll
    for (int u = 0; u < 4; u++) {
      float4 q0 = *(const float4*)(q_t + (ty*4+u)*64 + tx*8);
      float4 q1 = *(const float4*)(q_t + (ty*4+u)*64 + tx*8 + 4);
      float c0,c1,c2,c3,c4,c5,c6,c7;
      upk2(acc[u][0], c0, c1); upk2(acc[u][1], c2, c3);
      upk2(acc[u][2], c4, c5); upk2(acc[u][3], c6, c7);
      float p = c0*q0.x + c1*q0.y + c2*q0.z + c3*q0.w
              + c4*q1.x + c5*q1.y + c6*q1.z + c7*q1.w;
      p += __shfl_xor_sync(0xffffffffu, p, 1);
      p += __shfl_xor_sync(0xffffffffu, p, 2);
      p += __shfl_xor_sync(0xffffffffu, p, 4);
      if (tx == 0) att_sh[ty*4+u] += p;
    }
  }
  __syncthreads();
  for (int idx = tid; idx < DD*2; idx += 256) {
    int i = idx >> 1, p = idx & 1;
    *(float4*)(Msh + i*8 + p*4) = *(const float4*)(Mr + (size_t)i*DD + 192 + p*4);
  }
  for (int idx = tid; idx < ABM*2; idx += 256) {
    int e = idx >> 1, p = idx & 1;
    *(float4*)(q_t + e*8 + p*4) = *(const float4*)(Qbase + (size_t)es_dst[e]*DD + 192 + p*4);
  }
  __syncthreads();
  {
    int e = tid >> 1, half = tid & 1;
    ULL acc0 = pk2(0.f,0.f), acc1 = pk2(0.f,0.f);
    const float* krow = k_sh + e*KST;
    #pragma unroll 4
    for (int kk = 0; kk < DD; kk++) {
      float a = krow[kk];
      ULL aa = pk2(a, a);
      float4 mv = *(const float4*)(Msh + kk*8 + half*4);
      fma2(acc0, aa, ((const ULL*)&mv)[0]);
      fma2(acc1, aa, ((const ULL*)&mv)[1]);
    }
    float4 qv = *(const float4*)(q_t + e*8 + half*4);
    float s0,s1,s2,s3; upk2(acc0,s0,s1); upk2(acc1,s2,s3);
    float p = s0*qv.x + s1*qv.y + s2*qv.z + s3*qv.w;
    p += __shfl_xor_sync(0xffffffffu, p, 1);
    if (half == 0) att_sh[e] += p;
  }
  __syncthreads();
  if (tid < m) {
    float a = att_sh[tid];
    int e = es_eid[tid];
    g_att2[g_p2[e]] = a;
    unsigned u = __float_as_uint(a);
    u = (u & 0x80000000u) ? ~u : (u | 0x80000000u);
    atomicMax(&g_maxu[es_dst[tid]], u);
  }
}

// ---------------- per-dst softmax + weighted V aggregation + S merge --------------------
__device__ __forceinline__ float decf(unsigned u) {
  return (u & 0x80000000u) ? __uint_as_float(u ^ 0x80000000u) : __uint_as_float(~u);
}
__global__ __launch_bounds__(128) void k_agg2() {
  int d = blockIdx.x;
  int beg = g_off2[d], end = g_off2[d+1];
  int t = threadIdx.x;
  float m = decf(g_maxu[d]);
  float denom = 0.f;
  float ax = 0.f, ay = 0.f;
  const float* Vbase = g_KQVS + (size_t)2*NN*DD;
  if (beg < end) {
    float a_cur = g_att2[beg];
    int   s_cur = g_src2[beg];
    for (int i = beg; i < end; i++) {
      float a_nxt = 0.f; int s_nxt = 0;
      if (i + 1 < end) { a_nxt = g_att2[i+1]; s_nxt = g_src2[i+1]; }
      float ex = __expf(a_cur - m);
      denom += ex;
      if (t < 100) {
        float2 v = *(const float2*)(Vbase + (size_t)s_cur*DD + t*2);
        ax = fmaf(ex, v.x, ax);
        ay = fmaf(ex, v.y, ay);
      }
      a_cur = a_nxt; s_cur = s_nxt;
    }
  }
  if (t < 100) {
    float inv = (1.f/3.f) / fmaxf(denom, 1e-30f);
    size_t off = (size_t)d*DD + t*2;
    const float* Sb = g_KQVS + (size_t)3*NN*DD;
    float2 sv = *(const float2*)(Sb + off);
    float2 o;
    o.x = sv.x*(1.f/3.f) + ax*inv;
    o.y = sv.y*(1.f/3.f) + ay*inv;
    *(float2*)(g_agg + off) = o;
  }
}

// ---------------- column stats + bnprep (fused via last-block) ----------------
#define ST_ROWS 48
#define ST_GRID ((NN + ST_ROWS - 1)/ST_ROWS)
__global__ __launch_bounds__(256) void k_statsprep(const float* __restrict__ gamma,
                                                   const float* __restrict__ beta) {
  int c = threadIdx.x;
  int r0 = blockIdx.x*ST_ROWS;
  if (c < DD) {
    float s = 0.f, s2 = 0.f;
    int rmax = NN - r0; if (rmax > ST_ROWS) rmax = ST_ROWS;
    for (int lr = 0; lr < rmax; lr++) {
      float val = g_agg[(size_t)(r0+lr)*DD + c];
      s += val; s2 = fmaf(val, val, s2);
    }
    atomicAdd(&g_colsum[c], s);
    atomicAdd(&g_colsum2[c], s2);
  }
  __threadfence();
  __shared__ bool last;
  if (threadIdx.x == 0) last = (atomicAdd(&g_done, 1) == (int)gridDim.x - 1);
  __syncthreads();
  if (last && c < DD) {
    float mean = g_colsum[c] * (1.f/NN);
    float var  = g_colsum2[c] * (1.f/NN) - mean*mean;
    float sc = gamma[c] * rsqrtf(var + 1e-5f);
    g_scale[c] = sc;
    g_shift[c] = beta[c] - mean*sc;
  }
}

// ---------------- fused output: bnout + r_out ----------------
#define BNB ((NN*DD + 255)/256)   // 23438
__global__ __launch_bounds__(256) void k_outfused(const float* __restrict__ rf,
                                                  const float* __restrict__ br,
                                                  float* __restrict__ out) {
  __shared__ float xs[DD];
  int b = blockIdx.x;
  if (b < BNB) {
    int idx = b*256 + threadIdx.x;
    if (idx < NN*DD) {
      int c = idx - (idx/DD)*DD;
      float y = g_agg[idx]*g_scale[c] + g_shift[c];
      float t;
      asm("tanh.approx.f32 %0, %1;" : "=f"(t) : "f"(y));
      out[idx] = t;
    }
  } else {
    int r = b - BNB;
    int tid = threadIdx.x;
    if (tid < DD) xs[tid] = rf[(size_t)r*DD + tid];
    __syncthreads();
    if (tid < DD) {
      float acc = br[tid];
      for (int i = 0; i < DD; i++) acc = fmaf(xs[i], g_WRT[(size_t)i*DD + tid], acc);
      out[(size_t)NN*DD + (size_t)r*DD + tid] = acc;
    }
  }
}

// ---------------- launcher ----------------
extern "C" void kernel_launch(void* const* d_in, const int* in_sizes, int n_in,
                              void* d_out, int out_size) {
  const float* n_in_feats = (const float*)d_in[0];
  const float* r_feats    = (const float*)d_in[1];
  const float* loop_rel   = (const float*)d_in[3];
  const float* rel_att    = (const float*)d_in[4];
  const float* w_comp     = (const float*)d_in[5];
  const float* wS_w = (const float*)d_in[10]; const float* wS_b = (const float*)d_in[11];
  const float* wR_w = (const float*)d_in[12]; const float* wR_b = (const float*)d_in[13];
  const float* k_w  = (const float*)d_in[14]; const float* k_b  = (const float*)d_in[15];
  const float* q_w  = (const float*)d_in[16]; const float* q_b  = (const float*)d_in[17];
  const float* v_w  = (const float*)d_in[18]; const float* v_b  = (const float*)d_in[19];
  const float* gamma = (const float*)d_in[20]; const float* beta = (const float*)d_in[21];
  const int* src   = (const int*)d_in[22];
  const int* dst   = (const int*)d_in[23];
  const int* etype = (const int*)d_in[24];
  float* out = (float*)d_out;

  cudaFuncSetAttribute(k_gemm, cudaFuncAttributeMaxDynamicSharedMemorySize, GEMM_SMEM);
  cudaFuncSetAttribute(k_att,  cudaFuncAttributeMaxDynamicSharedMemorySize, ATT_SMEM);

  k_prep<<<PREP_GRID, 256>>>(k_w, q_w, v_w, wS_w, k_b, q_b, v_b, wS_b,
                             loop_rel, n_in_feats, wR_w);           // 1
  k_hist<<<(EE+255)/256, 256>>>(etype, dst);                        // 2
  k_compM<<<(DD*DD + 255)/256, 256>>>(rel_att, w_comp);             // 3
  {
    dim3 g((NN + GBM - 1)/GBM, (OUT4 + GBN - 1)/GBN);
    k_gemm<<<g, 512, GEMM_SMEM>>>();                                // 4 (ncu slot)
  }
  k_scan12<<<1, 1024>>>();                                          // 5
  k_scatter<<<(EE+255)/256, 256>>>(etype, src, dst);                // 6
  {
    dim3 g(RR, 16);
    k_att<<<g, 256, ATT_SMEM>>>(src, dst);                          // 7
  }
  k_agg2<<<NN, 128>>>();                                            // 8
  k_statsprep<<<ST_GRID, 256>>>(gamma, beta);                       // 9
  k_outfused<<<BNB + RR, 256>>>(r_feats, wR_b, out);                // 10
}

// round 17
// speedup vs baseline: 1.0319x; 1.0319x over previous
#include <cuda_runtime.h>
#include <cstdint>
#include <math.h>

#define NN 30000
#define EE 100000
#define DD 200
#define RR 100
#define BB 50
#define OUT4 (4*DD)   // 800 packed output columns: k,q,v,s

typedef unsigned long long ULL;

// ---------------- packed f32x2 helpers (FFMA2: 2x fp32 FMA throughput) ----------------
__device__ __forceinline__ ULL pk2(float a, float b) {
  ULL r; asm("mov.b64 %0,{%1,%2};" : "=l"(r) : "f"(a), "f"(b)); return r;
}
__device__ __forceinline__ void upk2(ULL d, float& x, float& y) {
  asm("mov.b64 {%0,%1},%2;" : "=f"(x), "=f"(y) : "l"(d));
}
__device__ __forceinline__ void fma2(ULL& d, ULL a, ULL b) {
  asm("fma.rn.f32x2 %0,%1,%2,%0;" : "+l"(d) : "l"(a), "l"(b));
}

// ---------------- scratch (static device globals; no runtime alloc) ----------------
__device__ __align__(16) float g_M[RR*DD*DD];        // per-relation matrices, 16MB
__device__ __align__(16) float g_W4T[DD*OUT4];       // packed weights, k-major [200][800]
__device__ __align__(16) float g_XT[DD*NN];          // transposed X, k-major [200][30000]
__device__ __align__(16) float g_WRT[DD*DD];         // transposed wR, k-major [200][200]
__device__ float g_b4[OUT4];
__device__ __align__(16) float g_KQVS[4u*NN*DD];     // K|Q|V|S node features, 96MB
__device__ unsigned g_maxu[NN];
__device__ __align__(16) float g_agg[NN*DD];         // n_pre (merged) output
__device__ int g_cnt[RR];
__device__ int g_off[RR+1];
__device__ int g_cur[RR];
__device__ int g_eid[EE];
__device__ int g_cnt2[NN];      // dst histogram
__device__ int g_off2[NN+1];
__device__ int g_cur2[NN];
__device__ int g_p2[EE];        // e -> dst-sorted position
__device__ int g_src2[EE];      // src, dst-sorted
__device__ float g_att2[EE];    // att, dst-sorted
__device__ float g_colsum[DD];
__device__ float g_colsum2[DD];
__device__ float g_scale[DD];
__device__ float g_shift[DD];
__device__ int g_done;

// ---------------- fused prep: pack W4T, biases, transpose X and wR, init counters -------
#define PB_PACK 625                      // OUT4*DD/256
#define PB_PACKB 25
#define NTX 938                          // ceil(NN/32)
#define PB_TX (NTX*7)                    // 6566
#define PB_TR 49                         // 7*7
#define PB_INIT 118                      // ceil(30000/256)
#define PREP_GRID (PB_PACK + PB_PACKB + PB_TX + PB_TR + PB_INIT)   // 7383
__global__ __launch_bounds__(256) void k_prep(
    const float* __restrict__ kw, const float* __restrict__ qw,
    const float* __restrict__ vw, const float* __restrict__ sw,
    const float* __restrict__ kb, const float* __restrict__ qb,
    const float* __restrict__ vb, const float* __restrict__ sb,
    const float* __restrict__ loop, const float* __restrict__ X,
    const float* __restrict__ wR) {
  __shared__ float tsh[32][33];
  int b = blockIdx.x, t = threadIdx.x;
  if (b < PB_PACK) {                         // ---- pack W4T[i][o]
    int idx = b*256 + t;
    if (idx < OUT4*DD) {
      int i = idx / OUT4, o = idx - i*OUT4;
      int z = o / DD, j = o - z*DD;
      const float* w = (z==0)?kw:(z==1)?qw:(z==2)?vw:sw;
      g_W4T[idx] = w[(size_t)j*DD + i];
    }
  } else if (b < PB_PACK + PB_PACKB) {       // ---- biases
    int blk = b - PB_PACK;
    int g = blk*256 + t;
    if (g < 600) {
      int z = g / DD, j = g - z*DD;
      g_b4[g] = (z==0)?kb[j]:(z==1)?qb[j]:vb[j];
    }
    int w = blk*8 + (t >> 5);
    int lane = t & 31;
    if (w < DD) {
      float acc = 0.f;
      for (int i = lane; i < DD; i += 32) acc = fmaf(loop[i], sw[(size_t)w*DD + i], acc);
      #pragma unroll
      for (int o = 16; o; o >>= 1) acc += __shfl_xor_sync(0xffffffffu, acc, o);
      if (lane == 0) g_b4[600 + w] = sb[w] - acc;
    }
  } else if (b < PB_PACK + PB_PACKB + PB_TX) {  // ---- transpose X
    int b2 = b - (PB_PACK + PB_PACKB);
    int bxi = (b2 % NTX)*32, byi = (b2 / NTX)*32;
    int tx = t & 31, ty = t >> 5;
    #pragma unroll
    for (int i = 0; i < 32; i += 8) {
      int n = bxi + ty + i, d = byi + tx;
      tsh[ty+i][tx] = (n < NN && d < DD) ? X[(size_t)n*DD + d] : 0.f;
    }
    __syncthreads();
    #pragma unroll
    for (int i = 0; i < 32; i += 8) {
      int d = byi + ty + i, n = bxi + tx;
      if (d < DD && n < NN) g_XT[(size_t)d*NN + n] = tsh[tx][ty+i];
    }
  } else if (b < PB_PACK + PB_PACKB + PB_TX + PB_TR) {  // ---- transpose wR
    int b2 = b - (PB_PACK + PB_PACKB + PB_TX);
    int bxi = (b2 % 7)*32, byi = (b2 / 7)*32;
    int tx = t & 31, ty = t >> 5;
    #pragma unroll
    for (int i = 0; i < 32; i += 8) {
      int j = bxi + ty + i, c = byi + tx;
      tsh[ty+i][tx] = (j < DD && c < DD) ? wR[(size_t)j*DD + c] : 0.f;
    }
    __syncthreads();
    #pragma unroll
    for (int i = 0; i < 32; i += 8) {
      int c = byi + ty + i, j = bxi + tx;
      if (c < DD && j < DD) g_WRT[(size_t)c*DD + j] = tsh[tx][ty+i];
    }
  } else {                                   // ---- init counters
    int idx = (b - (PB_PACK + PB_PACKB + PB_TX + PB_TR))*256 + t;
    if (idx < NN) { g_maxu[idx] = 0x007FFFFFu; g_cnt2[idx] = 0; g_cur2[idx] = 0; }
    if (idx < RR) { g_cnt[idx] = 0; g_cur[idx] = 0; }
    if (idx < DD) { g_colsum[idx] = 0.f; g_colsum2[idx] = 0.f; }
    if (idx == 0) g_done = 0;
  }
}

// ---------------- fused GEMM -> K,Q,V,S (f32x2, 512 threads, GBK=40; round-15 best) ----
#define GBM 128
#define GBN 128
#define GBK 40
#define NPH 5
#define GSTG (GBK*GBM)            // 5120 floats per matrix per buffer
#define GEMM_SMEM (4*GSTG*4)      // 81920 B : A0|A1|B0|B1
__global__ __launch_bounds__(512) void k_gemm() {
  extern __shared__ __align__(16) float sm[];
  float* Ab[2] = { sm,            sm + GSTG   };
  float* Bb[2] = { sm + 2*GSTG,   sm + 3*GSTG };
  int row0 = blockIdx.x*GBM, col0 = blockIdx.y*GBN;
  int tid = threadIdx.x;
  int gm_c = (tid & 31)*4;                  // col within tile row
  bool okA = (row0 + gm_c + 3 < NN);
  bool okB = (col0 + gm_c + 3 < OUT4);

  float4 rA[3], rB[3];
  #define LD_PH(s) do { \
    int k0 = (s)*GBK; \
    _Pragma("unroll") \
    for (int l = 0; l < 3; l++) { \
      int idx = tid + l*512; \
      if (idx < GSTG/4) { \
        int r = idx >> 5, c = idx & 31; \
        rA[l] = okA ? *(const float4*)(g_XT  + (size_t)(k0+r)*NN   + row0 + c*4) \
                    : make_float4(0.f,0.f,0.f,0.f); \
        rB[l] = okB ? *(const float4*)(g_W4T + (size_t)(k0+r)*OUT4 + col0 + c*4) \
                    : make_float4(0.f,0.f,0.f,0.f); \
      } \
    } \
  } while(0)
  #define ST_PH(b) do { \
    _Pragma("unroll") \
    for (int l = 0; l < 3; l++) { \
      int idx = tid + l*512; \
      if (idx < GSTG/4) { \
        int r = idx >> 5, c = idx & 31; \
        *(float4*)&Ab[b][r*GBM + c*4] = rA[l]; \
        *(float4*)&Bb[b][r*GBN + c*4] = rB[l]; \
      } \
    } \
  } while(0)

  // 4x4 warps (32x32 warp tile), lanes 4x8, 8x4 thread tile
  int w = tid >> 5, lane = tid & 31;
  int wm = w & 3, wn = w >> 2;
  int lm = lane >> 3, ln = lane & 7;
  int m0 = wm*32 + lm*8;
  int n0 = wn*32 + ln*4;

  ULL acc[8][2];
  #pragma unroll
  for (int u = 0; u < 8; u++) { acc[u][0] = pk2(0.f,0.f); acc[u][1] = pk2(0.f,0.f); }

  LD_PH(0); ST_PH(0);
  __syncthreads();
  #pragma unroll
  for (int s = 0; s < NPH; s++) {
    int b = s & 1;
    if (s + 1 < NPH) LD_PH(s+1);      // LDG in flight during compute below
    const float* A = Ab[b];
    const float* B = Bb[b];
    #pragma unroll 4
    for (int kk = 0; kk < GBK; kk++) {
      float4 a0 = *(const float4*)&A[kk*GBM + m0];
      float4 a1 = *(const float4*)&A[kk*GBM + m0 + 4];
      float4 b0 = *(const float4*)&B[kk*GBN + n0];
      ULL bb0 = ((const ULL*)&b0)[0], bb1 = ((const ULL*)&b0)[1];
      float av[8] = {a0.x,a0.y,a0.z,a0.w,a1.x,a1.y,a1.z,a1.w};
      #pragma unroll
      for (int u = 0; u < 8; u++) {
        ULL aa = pk2(av[u], av[u]);
        fma2(acc[u][0], aa, bb0);
        fma2(acc[u][1], aa, bb1);
      }
    }
    if (s + 1 < NPH) ST_PH((s+1)&1);  // other buffer; prior readers done (sync below)
    __syncthreads();
  }

  // epilogue: 8 rows x 4 cols per thread; 4-col groups never straddle z-boundary
  int o0 = col0 + n0;
  if (o0 < OUT4) {
    int z = o0 / DD, j0 = o0 - z*DD;
    float4 bi = *(const float4*)&g_b4[o0];
    float* outb = g_KQVS + (size_t)z*NN*DD + j0;
    #pragma unroll
    for (int u = 0; u < 8; u++) {
      int n = row0 + m0 + u;
      if (n >= NN) continue;
      float c0,c1,c2,c3;
      upk2(acc[u][0], c0, c1); upk2(acc[u][1], c2, c3);
      *(float4*)(outb + (size_t)n*DD) =
        make_float4(c0+bi.x, c1+bi.y, c2+bi.z, c3+bi.w);
    }
  }
  #undef LD_PH
  #undef ST_PH
}

// ---------------- M_r = sum_b w_comp[r,b] * A_b  (register-cached) ----------------
__global__ __launch_bounds__(256) void k_compM(const float* __restrict__ A,
                                               const float* __restrict__ wc) {
  __shared__ float wsh[RR*BB];   // 20KB
  int tid = threadIdx.x;
  for (int idx = tid; idx < RR*BB; idx += 256) wsh[idx] = wc[idx];
  __syncthreads();
  int n = blockIdx.x*256 + tid;
  if (n >= DD*DD) return;
  float a[BB];
  #pragma unroll
  for (int b = 0; b < BB; b++) a[b] = A[(size_t)b*DD*DD + n];
  for (int r = 0; r < RR; r++) {
    float acc0 = 0.f, acc1 = 0.f;
    const float* wr = wsh + r*BB;
    #pragma unroll
    for (int b = 0; b < BB; b += 2) {
      acc0 = fmaf(wr[b],   a[b],   acc0);
      acc1 = fmaf(wr[b+1], a[b+1], acc1);
    }
    g_M[(size_t)r*DD*DD + n] = acc0 + acc1;
  }
}

// ---------------- histograms: by relation AND by dst ----------------
__global__ void k_hist(const int* __restrict__ et, const int* __restrict__ dst) {
  int e = blockIdx.x*blockDim.x + threadIdx.x;
  if (e < EE) {
    atomicAdd(&g_cnt[et[e]], 1);
    atomicAdd(&g_cnt2[dst[e]], 1);
  }
}

// ---------------- fused scans: relation offsets (parallel) + dst offsets ----------------
#define SC_CHUNK 30
__global__ __launch_bounds__(1024) void k_scan12() {
  __shared__ int ps[1024];
  __shared__ int rs[128];
  int t = threadIdx.x;
  if (t < 128) rs[t] = (t < RR) ? g_cnt[t] : 0;
  __syncthreads();
  for (int off = 1; off < 128; off <<= 1) {
    int a = 0;
    if (t < 128) { a = rs[t]; if (t >= off) a += rs[t-off]; }
    __syncthreads();
    if (t < 128) rs[t] = a;
    __syncthreads();
  }
  if (t < RR) g_off[t] = (t == 0) ? 0 : rs[t-1];
  if (t == 0) g_off[RR] = rs[RR-1];
  __syncthreads();
  int base = t*SC_CHUNK;
  int s = 0;
  #pragma unroll
  for (int i = 0; i < SC_CHUNK; i++) { int idx = base+i; if (idx < NN) s += g_cnt2[idx]; }
  ps[t] = s;
  __syncthreads();
  for (int off = 1; off < 1024; off <<= 1) {
    int v = ps[t];
    int add = (t >= off) ? ps[t-off] : 0;
    __syncthreads();
    ps[t] = v + add;
    __syncthreads();
  }
  int run = (t > 0) ? ps[t-1] : 0;
  #pragma unroll
  for (int i = 0; i < SC_CHUNK; i++) {
    int idx = base+i;
    if (idx < NN) { g_off2[idx] = run; run += g_cnt2[idx]; }
  }
  if (t == 1023) g_off2[NN] = ps[1023];
}
__global__ void k_scatter(const int* __restrict__ et, const int* __restrict__ src,
                          const int* __restrict__ dst) {
  int e = blockIdx.x*blockDim.x + threadIdx.x;
  if (e < EE) {
    int t = et[e];
    int p = atomicAdd(&g_cur[t], 1);
    g_eid[g_off[t] + p] = e;
    int d = dst[e];
    int p2 = atomicAdd(&g_cur2[d], 1);
    int pos = g_off2[d] + p2;
    g_p2[e] = pos;
    g_src2[pos] = src[e];
  }
}

// ---------------- attention: att_e = k^T M_r q (f32x2), 256 thr, 4 rows/thread ----------
#define ABM 128
#define KST 204
#define ATT_SMEM ((ABM*KST + DD*64 + ABM*64 + ABM)*4 + 3*ABM*4)  // 190464 B
__global__ __launch_bounds__(256, 1) void k_att(const int* __restrict__ src,
                                                const int* __restrict__ dst) {
  extern __shared__ __align__(16) float sm[];
  float* k_sh   = sm;                 // [ABM][KST]
  float* Msh    = k_sh + ABM*KST;     // [DD][64] (reused as [DD][8] in remainder)
  float* q_t    = Msh + DD*64;        // [ABM][64] (reused as [ABM][8])
  float* att_sh = q_t + ABM*64;       // [ABM]
  int* es_src = (int*)(att_sh + ABM);
  int* es_dst = es_src + ABM;
  int* es_eid = es_dst + ABM;

  int r = blockIdx.x;
  int beg = g_off[r], end = g_off[r+1];
  int base = beg + blockIdx.y*ABM;
  if (base >= end) return;
  int m = end - base; if (m > ABM) m = ABM;
  int tid = threadIdx.x;
  if (tid < ABM) {
    int e = g_eid[base + ((tid < m) ? tid : 0)];
    es_eid[tid] = e;
    es_src[tid] = src[e];
    es_dst[tid] = dst[e];
    att_sh[tid] = 0.f;
  }
  __syncthreads();
  for (int idx = tid; idx < ABM*(DD/4); idx += 256) {
    int e = idx / (DD/4), p = idx - e*(DD/4);
    *(float4*)(k_sh + e*KST + p*4) = *(const float4*)(g_KQVS + (size_t)es_src[e]*DD + p*4);
  }
  int tx = tid & 7;
  int ty = tid >> 3;        // 0..31, 4 rows each
  const float* Mr = g_M + (size_t)r*DD*DD;
  const float* Qbase = g_KQVS + (size_t)NN*DD;
  for (int jt = 0; jt < 3; jt++) {
    int j0 = jt*64;
    __syncthreads();
    for (int idx = tid; idx < DD*16; idx += 256) {
      int i = idx >> 4, p = idx & 15;
      *(float4*)(Msh + i*64 + p*4) = *(const float4*)(Mr + (size_t)i*DD + j0 + p*4);
    }
    for (int idx = tid; idx < ABM*16; idx += 256) {
      int e = idx >> 4, p = idx & 15;
      *(float4*)(q_t + e*64 + p*4) = *(const float4*)(Qbase + (size_t)es_dst[e]*DD + j0 + p*4);
    }
    __syncthreads();
    ULL acc[4][4];
    #pragma unroll
    for (int u = 0; u < 4; u++)
      #pragma unroll
      for (int v = 0; v < 4; v++) acc[u][v] = pk2(0.f, 0.f);
    #pragma unroll 4
    for (int kk = 0; kk < DD; kk++) {
      float4 b0 = *(const float4*)(Msh + kk*64 + tx*8);
      float4 b1 = *(const float4*)(Msh + kk*64 + tx*8 + 4);
      ULL bb0 = ((const ULL*)&b0)[0], bb1 = ((const ULL*)&b0)[1];
      ULL bb2 = ((const ULL*)&b1)[0], bb3 = ((const ULL*)&b1)[1];
      #pragma unroll
      for (int u = 0; u < 4; u++) {
        float a = k_sh[(ty*4+u)*KST + kk];
        ULL aa = pk2(a, a);
        fma2(acc[u][0], aa, bb0); fma2(acc[u][1], aa, bb1);
        fma2(acc[u][2], aa, bb2); fma2(acc[u][3], aa, bb3);
      }
    }
    #pragma unroll
    for (int u = 0; u < 4; u++) {
      float4 q0 = *(const float4*)(q_t + (ty*4+u)*64 + tx*8);
      float4 q1 = *(const float4*)(q_t + (ty*4+u)*64 + tx*8 + 4);
      float c0,c1,c2,c3,c4,c5,c6,c7;
      upk2(acc[u][0], c0, c1); upk2(acc[u][1], c2, c3);
      upk2(acc[u][2], c4, c5); upk2(acc[u][3], c6, c7);
      float p = c0*q0.x + c1*q0.y + c2*q0.z + c3*q0.w
              + c4*q1.x + c5*q1.y + c6*q1.z + c7*q1.w;
      p += __shfl_xor_sync(0xffffffffu, p, 1);
      p += __shfl_xor_sync(0xffffffffu, p, 2);
      p += __shfl_xor_sync(0xffffffffu, p, 4);
      if (tx == 0) att_sh[ty*4+u] += p;
    }
  }
  __syncthreads();
  for (int idx = tid; idx < DD*2; idx += 256) {
    int i = idx >> 1, p = idx & 1;
    *(float4*)(Msh + i*8 + p*4) = *(const float4*)(Mr + (size_t)i*DD + 192 + p*4);
  }
  for (int idx = tid; idx < ABM*2; idx += 256) {
    int e = idx >> 1, p = idx & 1;
    *(float4*)(q_t + e*8 + p*4) = *(const float4*)(Qbase + (size_t)es_dst[e]*DD + 192 + p*4);
  }
  __syncthreads();
  {
    int e = tid >> 1, half = tid & 1;
    ULL acc0 = pk2(0.f,0.f), acc1 = pk2(0.f,0.f);
    const float* krow = k_sh + e*KST;
    #pragma unroll 4
    for (int kk = 0; kk < DD; kk++) {
      float a = krow[kk];
      ULL aa = pk2(a, a);
      float4 mv = *(const float4*)(Msh + kk*8 + half*4);
      fma2(acc0, aa, ((const ULL*)&mv)[0]);
      fma2(acc1, aa, ((const ULL*)&mv)[1]);
    }
    float4 qv = *(const float4*)(q_t + e*8 + half*4);
    float s0,s1,s2,s3; upk2(acc0,s0,s1); upk2(acc1,s2,s3);
    float p = s0*qv.x + s1*qv.y + s2*qv.z + s3*qv.w;
    p += __shfl_xor_sync(0xffffffffu, p, 1);
    if (half == 0) att_sh[e] += p;
  }
  __syncthreads();
  if (tid < m) {
    float a = att_sh[tid];
    int e = es_eid[tid];
    g_att2[g_p2[e]] = a;
    unsigned u = __float_as_uint(a);
    u = (u & 0x80000000u) ? ~u : (u | 0x80000000u);
    atomicMax(&g_maxu[es_dst[tid]], u);
  }
}

// ---------------- per-dst softmax + weighted V aggregation + S merge --------------------
__device__ __forceinline__ float decf(unsigned u) {
  return (u & 0x80000000u) ? __uint_as_float(u ^ 0x80000000u) : __uint_as_float(~u);
}
__global__ __launch_bounds__(128) void k_agg2() {
  int d = blockIdx.x;
  int beg = g_off2[d], end = g_off2[d+1];
  int t = threadIdx.x;
  float m = decf(g_maxu[d]);
  float denom = 0.f;
  float ax = 0.f, ay = 0.f;
  const float* Vbase = g_KQVS + (size_t)2*NN*DD;
  if (beg < end) {
    float a_cur = g_att2[beg];
    int   s_cur = g_src2[beg];
    for (int i = beg; i < end; i++) {
      float a_nxt = 0.f; int s_nxt = 0;
      if (i + 1 < end) { a_nxt = g_att2[i+1]; s_nxt = g_src2[i+1]; }
      float ex = __expf(a_cur - m);
      denom += ex;
      if (t < 100) {
        float2 v = *(const float2*)(Vbase + (size_t)s_cur*DD + t*2);
        ax = fmaf(ex, v.x, ax);
        ay = fmaf(ex, v.y, ay);
      }
      a_cur = a_nxt; s_cur = s_nxt;
    }
  }
  if (t < 100) {
    float inv = (1.f/3.f) / fmaxf(denom, 1e-30f);
    size_t off = (size_t)d*DD + t*2;
    const float* Sb = g_KQVS + (size_t)3*NN*DD;
    float2 sv = *(const float2*)(Sb + off);
    float2 o;
    o.x = sv.x*(1.f/3.f) + ax*inv;
    o.y = sv.y*(1.f/3.f) + ay*inv;
    *(float2*)(g_agg + off) = o;
  }
}

// ---------------- column stats + bnprep (fused via last-block) ----------------
#define ST_ROWS 48
#define ST_GRID ((NN + ST_ROWS - 1)/ST_ROWS)
__global__ __launch_bounds__(256) void k_statsprep(const float* __restrict__ gamma,
                                                   const float* __restrict__ beta) {
  int c = threadIdx.x;
  int r0 = blockIdx.x*ST_ROWS;
  if (c < DD) {
    float s = 0.f, s2 = 0.f;
    int rmax = NN - r0; if (rmax > ST_ROWS) rmax = ST_ROWS;
    for (int lr = 0; lr < rmax; lr++) {
      float val = g_agg[(size_t)(r0+lr)*DD + c];
      s += val; s2 = fmaf(val, val, s2);
    }
    atomicAdd(&g_colsum[c], s);
    atomicAdd(&g_colsum2[c], s2);
  }
  __threadfence();
  __shared__ bool last;
  if (threadIdx.x == 0) last = (atomicAdd(&g_done, 1) == (int)gridDim.x - 1);
  __syncthreads();
  if (last && c < DD) {
    float mean = g_colsum[c] * (1.f/NN);
    float var  = g_colsum2[c] * (1.f/NN) - mean*mean;
    float sc = gamma[c] * rsqrtf(var + 1e-5f);
    g_scale[c] = sc;
    g_shift[c] = beta[c] - mean*sc;
  }
}

// ---------------- fused output: bnout + r_out ----------------
#define BNB ((NN*DD + 255)/256)   // 23438
__global__ __launch_bounds__(256) void k_outfused(const float* __restrict__ rf,
                                                  const float* __restrict__ br,
                                                  float* __restrict__ out) {
  __shared__ float xs[DD];
  int b = blockIdx.x;
  if (b < BNB) {
    int idx = b*256 + threadIdx.x;
    if (idx < NN*DD) {
      int c = idx - (idx/DD)*DD;
      float y = g_agg[idx]*g_scale[c] + g_shift[c];
      float t;
      asm("tanh.approx.f32 %0, %1;" : "=f"(t) : "f"(y));
      out[idx] = t;
    }
  } else {
    int r = b - BNB;
    int tid = threadIdx.x;
    if (tid < DD) xs[tid] = rf[(size_t)r*DD + tid];
    __syncthreads();
    if (tid < DD) {
      float acc = br[tid];
      for (int i = 0; i < DD; i++) acc = fmaf(xs[i], g_WRT[(size_t)i*DD + tid], acc);
      out[(size_t)NN*DD + (size_t)r*DD + tid] = acc;
    }
  }
}

// ---------------- launcher ----------------
extern "C" void kernel_launch(void* const* d_in, const int* in_sizes, int n_in,
                              void* d_out, int out_size) {
  const float* n_in_feats = (const float*)d_in[0];
  const float* r_feats    = (const float*)d_in[1];
  const float* loop_rel   = (const float*)d_in[3];
  const float* rel_att    = (const float*)d_in[4];
  const float* w_comp     = (const float*)d_in[5];
  const float* wS_w = (const float*)d_in[10]; const float* wS_b = (const float*)d_in[11];
  const float* wR_w = (const float*)d_in[12]; const float* wR_b = (const float*)d_in[13];
  const float* k_w  = (const float*)d_in[14]; const float* k_b  = (const float*)d_in[15];
  const float* q_w  = (const float*)d_in[16]; const float* q_b  = (const float*)d_in[17];
  const float* v_w  = (const float*)d_in[18]; const float* v_b  = (const float*)d_in[19];
  const float* gamma = (const float*)d_in[20]; const float* beta = (const float*)d_in[21];
  const int* src   = (const int*)d_in[22];
  const int* dst   = (const int*)d_in[23];
  const int* etype = (const int*)d_in[24];
  float* out = (float*)d_out;

  cudaFuncSetAttribute(k_gemm, cudaFuncAttributeMaxDynamicSharedMemorySize, GEMM_SMEM);
  cudaFuncSetAttribute(k_att,  cudaFuncAttributeMaxDynamicSharedMemorySize, ATT_SMEM);

  k_prep<<<PREP_GRID, 256>>>(k_w, q_w, v_w, wS_w, k_b, q_b, v_b, wS_b,
                             loop_rel, n_in_feats, wR_w);           // 1
  k_hist<<<(EE+255)/256, 256>>>(etype, dst);                        // 2
  k_compM<<<(DD*DD + 255)/256, 256>>>(rel_att, w_comp);             // 3
  {
    dim3 g((NN + GBM - 1)/GBM, (OUT4 + GBN - 1)/GBN);
    k_gemm<<<g, 512, GEMM_SMEM>>>();                                // 4 (ncu slot)
  }
  k_scan12<<<1, 1024>>>();                                          // 5
  k_scatter<<<(EE+255)/256, 256>>>(etype, src, dst);                // 6
  {
    dim3 g(RR, 16);
    k_att<<<g, 256, ATT_SMEM>>>(src, dst);                          // 7
  }
  k_agg2<<<NN, 128>>>();                                            // 8
  k_statsprep<<<ST_GRID, 256>>>(gamma, beta);                       // 9
  k_outfused<<<BNB + RR, 256>>>(r_feats, wR_b, out);                // 10
}